// round 13
// baseline (speedup 1.0000x reference)
#include <cuda_runtime.h>
#include <cuda_bf16.h>
#include <cstdint>

#define NB 64
#define NN 1024
#define ND 16
#define TILE_M 128
#define TILES (NN / TILE_M)     // 8
#define NCTAS (NB * TILES)      // 512
#define THREADS 128
#define WARPS 4
#define CHUNK 64
#define NCHUNK (NN / CHUNK)     // 16

// ---- shared memory layout (byte offsets) ----
#define SM_FT   0               // F bf16 [1024 nodes][16 dims], swizzled 32-B rows: 32768 B
#define SM_A    32768           // A-tiles bf16: 4 warps x 2 strips x 2048 B = 16384 B
#define SM_WS2  49152           // 4 f32
#define SM_WC   49168           // 4 f32
#define SM_LAST 49184           // 1 int
#define SMEM_TOTAL 49216

#define BONES 0x3F803F80u       // bf16x2 (1.0, 1.0)

__device__ float g_scratch[NCTAS];
__device__ unsigned int g_count;   // zero-init; reset by last CTA each launch

// ---------------- helpers ----------------
__device__ __forceinline__ uint32_t smem_u32(const void* p) {
    uint32_t a;
    asm("{ .reg .u64 t; cvta.to.shared.u64 t, %1; cvt.u32.u64 %0, t; }" : "=r"(a) : "l"(p));
    return a;
}
__device__ __forceinline__ unsigned long long fma2(unsigned long long a, unsigned long long b,
                                                   unsigned long long c) {
    unsigned long long d;
    asm("fma.rn.f32x2 %0, %1, %2, %3;" : "=l"(d) : "l"(a), "l"(b), "l"(c));
    return d;
}
__device__ __forceinline__ unsigned long long pack2(float x, float y) {
    unsigned long long d;
    asm("mov.b64 %0, {%1, %2};" : "=l"(d) : "f"(x), "f"(y));
    return d;
}
__device__ __forceinline__ void unpack2(unsigned long long v, float& x, float& y) {
    asm("mov.b64 {%0, %1}, %2;" : "=f"(x), "=f"(y) : "l"(v));
}
__device__ __forceinline__ uint32_t cvt2(float a, float b) {
    uint32_t r;
    asm("cvt.rn.bf16x2.f32 %0, %1, %2;" : "=r"(r) : "f"(b), "f"(a));
    return r;
}
__device__ __forceinline__ void sts_v2(uint32_t addr, uint32_t r0, uint32_t r1) {
    asm volatile("st.shared.v2.b32 [%0], {%1, %2};" :: "r"(addr), "r"(r0), "r"(r1) : "memory");
}
__device__ __forceinline__ void ldsm_x4(uint32_t addr, uint32_t& r0, uint32_t& r1,
                                        uint32_t& r2, uint32_t& r3) {
    asm volatile("ldmatrix.sync.aligned.m8n8.x4.shared.b16 {%0,%1,%2,%3}, [%4];"
                 : "=r"(r0), "=r"(r1), "=r"(r2), "=r"(r3) : "r"(addr));
}
__device__ __forceinline__ void ldsm_x4_t(uint32_t addr, uint32_t& r0, uint32_t& r1,
                                          uint32_t& r2, uint32_t& r3) {
    asm volatile("ldmatrix.sync.aligned.m8n8.x4.trans.shared.b16 {%0,%1,%2,%3}, [%4];"
                 : "=r"(r0), "=r"(r1), "=r"(r2), "=r"(r3) : "r"(addr));
}
__device__ __forceinline__ void mma16816(float* d, uint32_t a0, uint32_t a1, uint32_t a2,
                                         uint32_t a3, uint32_t b0, uint32_t b1) {
    asm volatile(
        "mma.sync.aligned.m16n8k16.row.col.f32.bf16.bf16.f32 "
        "{%0,%1,%2,%3}, {%4,%5,%6,%7}, {%8,%9}, {%0,%1,%2,%3};"
        : "+f"(d[0]), "+f"(d[1]), "+f"(d[2]), "+f"(d[3])
        : "r"(a0), "r"(a1), "r"(a2), "r"(a3), "r"(b0), "r"(b1));
}

// ---------------- main kernel ----------------
__global__ __launch_bounds__(THREADS, 4)
void graph_loss_main(const float* __restrict__ A, const float* __restrict__ F,
                     float* __restrict__ out) {
    extern __shared__ __align__(1024) char smem[];
    const uint32_t sb = smem_u32(smem);

    const int b    = blockIdx.y;
    const int tile = blockIdx.x;
    const int row0 = tile * TILE_M;
    const int tid  = threadIdx.x;
    const int wid  = tid >> 5;
    const int lane = tid & 31;

    // ---- stage F bf16 node-major [k][16 dims], 32-B rows, unit-swizzled ----
    {
        const float4* F4 = (const float4*)(F + (size_t)b * NN * ND);
        for (int i = tid; i < NN * ND / 4; i += THREADS) {
            const int k = i >> 2, q = i & 3;
            float4 v = F4[i];
            uint32_t lo = cvt2(v.x, v.y), hi = cvt2(v.z, v.w);
            uint32_t off = (uint32_t)(k * 32) +
                           ((uint32_t)(((q >> 1) ^ ((k >> 2) & 1)) << 4)) +
                           ((uint32_t)((q & 1) << 3));
            sts_v2(sb + SM_FT + off, lo, hi);
        }
    }
    __syncthreads();

    // warp owns 32 rows: strip0 = rows [wid*32, +16), strip1 = [wid*32+16, +16)
    const float* Arow0 = A + ((size_t)b * NN + row0 + wid * 32) * NN;
    const float* Arow1 = Arow0 + (size_t)16 * NN;
    const uint32_t abase0 = sb + SM_A + wid * 4096;
    const uint32_t abase1 = abase0 + 2048;

    float D0[2][4] = {{0.f,0.f,0.f,0.f},{0.f,0.f,0.f,0.f}};  // dims 0-7
    float D1[2][4] = {{0.f,0.f,0.f,0.f},{0.f,0.f,0.f,0.f}};  // dims 8-15
    float D2[2][4] = {{0.f,0.f,0.f,0.f},{0.f,0.f,0.f,0.f}};  // deg (B = ones)
    unsigned long long s22 = 0ULL;

    const int lrow = lane >> 4;
    const int lq   = lane & 15;
    const int lm   = lane >> 3;
    const int lr   = lane & 7;
    const int arow = ((lm & 1) << 3) + lr;        // A frag row 0..15
    const int ac   = lm >> 1;                     // A frag k-half
    const int bk   = ((lm & 1) << 3) + lr;        // B (trans) k-row
    const int bu   = lm >> 1;                     // B n-half unit
    const uint32_t bbase = sb + SM_FT +
        (uint32_t)(bk * 32 + ((bu ^ ((bk >> 2) & 1)) << 4));  // lane-constant

    auto load8 = [&](float4* v, const float* Arow, int ch) {
        const int c0 = ch * CHUNK;
#pragma unroll
        for (int p = 0; p < 8; ++p)
            v[p] = __ldcs((const float4*)(Arow + (size_t)(2 * p + lrow) * NN + c0) + lq);
    };
    auto process = [&](const float4* v, int ch, uint32_t a_base,
                       float* P0, float* P1, float* P2) {
#pragma unroll
        for (int p = 0; p < 8; ++p) {
            unsigned long long p0 = pack2(v[p].x, v[p].y);
            unsigned long long p1 = pack2(v[p].z, v[p].w);
            s22 = fma2(p0, p0, s22);
            s22 = fma2(p1, p1, s22);
            const int row = 2 * p + lrow;
            uint32_t byte = (uint32_t)(lq * 8) ^ ((uint32_t)(row & 7) << 4);
            sts_v2(a_base + row * 128 + byte, cvt2(v[p].x, v[p].y), cvt2(v[p].z, v[p].w));
        }
        __syncwarp();
#pragma unroll
        for (int kk = 0; kk < 4; ++kk) {
            uint32_t abyte = (uint32_t)(kk * 32 + ac * 16) ^ ((uint32_t)(arow & 7) << 4);
            uint32_t a0, a1, a2, a3;
            ldsm_x4(a_base + arow * 128 + abyte, a0, a1, a2, a3);

            uint32_t b0, b1, b2, b3;
            ldsm_x4_t(bbase + (uint32_t)(ch * 2048 + kk * 512), b0, b1, b2, b3);

            mma16816(P0, a0, a1, a2, a3, b0, b1);
            mma16816(P1, a0, a1, a2, a3, b2, b3);
            mma16816(P2, a0, a1, a2, a3, BONES, BONES);   // row degrees
        }
        __syncwarp();
    };

    // ---- software-pipelined main loop: the two strips ARE the two buffers ----
    float4 va[8], vb[8];
    load8(va, Arow0, 0);
#pragma unroll 1
    for (int ch = 0; ch < NCHUNK; ++ch) {
        load8(vb, Arow1, ch);
        process(va, ch, abase0, D0[0], D1[0], D2[0]);
        if (ch + 1 < NCHUNK) load8(va, Arow0, ch + 1);
        process(vb, ch, abase1, D0[1], D1[1], D2[1]);
    }

    float* ws2   = (float*)(smem + SM_WS2);
    float* wc    = (float*)(smem + SM_WC);
    int*   lastf = (int*)(smem + SM_LAST);

    // ---- s2 warp reduction ----
    {
        float lo, hi;
        unpack2(s22, lo, hi);
        float s2t = lo + hi;
#pragma unroll
        for (int off = 16; off; off >>= 1) s2t += __shfl_xor_sync(0xffffffffu, s2t, off);
        if (lane == 0) ws2[wid] = s2t;
    }

    // ---- fragment-space epilogue: dt/ff/deg per row from MMA fragments ----
    const float C1 = 0.2f / (float)(NN * NN);
    const float C2 = 0.1f / (float)NN;
    const float C3 = 0.1f / (float)(NN * NN);

    const int g = lane >> 2;       // row group 0..7
    const int c = lane & 3;        // col-pair 0..3
    const float* Fb = F + (size_t)b * NN * ND;
    float closs = 0.0f;
#pragma unroll
    for (int s = 0; s < 2; ++s) {
        const int r0 = row0 + wid * 32 + s * 16 + g;   // rows r0, r0+8
        float2 fA0 = *(const float2*)&Fb[(size_t)r0 * ND + 2 * c];
        float2 fB0 = *(const float2*)&Fb[(size_t)r0 * ND + 2 * c + 8];
        float2 fA1 = *(const float2*)&Fb[(size_t)(r0 + 8) * ND + 2 * c];
        float2 fB1 = *(const float2*)&Fb[(size_t)(r0 + 8) * ND + 2 * c + 8];

        float dt0 = fA0.x * D0[s][0] + fA0.y * D0[s][1] + fB0.x * D1[s][0] + fB0.y * D1[s][1];
        float dt1 = fA1.x * D0[s][2] + fA1.y * D0[s][3] + fB1.x * D1[s][2] + fB1.y * D1[s][3];
        float ff0 = fA0.x * fA0.x + fA0.y * fA0.y + fB0.x * fB0.x + fB0.y * fB0.y;
        float ff1 = fA1.x * fA1.x + fA1.y * fA1.y + fB1.x * fB1.x + fB1.y * fB1.y;
#pragma unroll
        for (int off = 1; off < 4; off <<= 1) {
            dt0 += __shfl_xor_sync(0xffffffffu, dt0, off);
            dt1 += __shfl_xor_sync(0xffffffffu, dt1, off);
            ff0 += __shfl_xor_sync(0xffffffffu, ff0, off);
            ff1 += __shfl_xor_sync(0xffffffffu, ff1, off);
        }
        if (c == 0) {
            const float d0 = D2[s][0];     // deg row r0 (all frag cols equal)
            const float d1 = D2[s][2];     // deg row r0+8
            closs += C1 * (d0 * ff0 - dt0) - C2 * logf(d0 + 1e-12f);
            closs += C1 * (d1 * ff1 - dt1) - C2 * logf(d1 + 1e-12f);
        }
    }
#pragma unroll
    for (int off = 16; off; off >>= 1) closs += __shfl_xor_sync(0xffffffffu, closs, off);
    if (lane == 0) wc[wid] = closs;
    __syncthreads();

    // ---- write partial; last CTA reduces ----
    if (tid == 0) {
        float t = wc[0] + wc[1] + wc[2] + wc[3];
        float s2sum = ws2[0] + ws2[1] + ws2[2] + ws2[3];
        g_scratch[b * TILES + tile] = t + C3 * s2sum;
        __threadfence();
        unsigned int prev = atomicAdd(&g_count, 1u);
        *lastf = (prev == NCTAS - 1) ? 1 : 0;
    }
    __syncthreads();
    if (*lastf) {
        __threadfence();
        if (tid < NB) {
            float s = 0.f;
#pragma unroll
            for (int k = 0; k < TILES; k++) s += __ldcg(&g_scratch[tid * TILES + k]);
            out[tid] = s;
        }
        if (tid == 0) g_count = 0;
    }
}

extern "C" void kernel_launch(void* const* d_in, const int* in_sizes, int n_in,
                              void* d_out, int out_size) {
    const float* A = (const float*)d_in[0];   // out_adj  [64,1024,1024]
    const float* F = (const float*)d_in[1];   // features [64,1024,16]
    float* out = (float*)d_out;               // [64] fp32

    cudaFuncSetAttribute(graph_loss_main,
                         cudaFuncAttributeMaxDynamicSharedMemorySize, SMEM_TOTAL);
    dim3 grid(TILES, NB);
    graph_loss_main<<<grid, THREADS, SMEM_TOTAL>>>(A, F, out);
}

// round 14
// speedup vs baseline: 1.2470x; 1.2470x over previous
#include <cuda_runtime.h>
#include <cuda_bf16.h>
#include <cstdint>

#define NB 64
#define NN 1024
#define ND 16
#define TILE_M 256              // rows per CTA (two 128-row halves)
#define TILES (NN / TILE_M)     // 4
#define NCTAS (NB * TILES)      // 256  -> single wave at 2 CTAs/SM
#define THREADS 256
#define WARPS 8
#define CHUNK 64
#define NCHUNK (NN / CHUNK)     // 16

// ---- shared memory layout (byte offsets) ----
#define SM_FT   0               // F bf16 [1024 nodes][16 dims], swizzled 32-B rows: 32768 B
#define SM_A    32768           // A-tiles bf16: 8 warps x 2 bufs x 2048 B = 32768 B
#define SM_AF   65536           // af fp32 [128][16]: 8192 B
#define SM_DEG  73728           // 128 f32
#define SM_WS2  74240           // 8 f32
#define SM_WC   74272           // 4 f32
#define SM_LAST 74288           // 1 int
#define SMEM_TOTAL 74368

#define BONES 0x3F803F80u       // bf16x2 (1.0, 1.0)

__device__ float g_scratch[NCTAS];
__device__ unsigned int g_count;   // zero-init; reset by last CTA each launch

// ---------------- helpers ----------------
__device__ __forceinline__ uint32_t smem_u32(const void* p) {
    uint32_t a;
    asm("{ .reg .u64 t; cvta.to.shared.u64 t, %1; cvt.u32.u64 %0, t; }" : "=r"(a) : "l"(p));
    return a;
}
__device__ __forceinline__ unsigned long long fma2(unsigned long long a, unsigned long long b,
                                                   unsigned long long c) {
    unsigned long long d;
    asm("fma.rn.f32x2 %0, %1, %2, %3;" : "=l"(d) : "l"(a), "l"(b), "l"(c));
    return d;
}
__device__ __forceinline__ unsigned long long pack2(float x, float y) {
    unsigned long long d;
    asm("mov.b64 %0, {%1, %2};" : "=l"(d) : "f"(x), "f"(y));
    return d;
}
__device__ __forceinline__ void unpack2(unsigned long long v, float& x, float& y) {
    asm("mov.b64 {%0, %1}, %2;" : "=f"(x), "=f"(y) : "l"(v));
}
__device__ __forceinline__ uint32_t cvt2(float a, float b) {
    uint32_t r;
    asm("cvt.rn.bf16x2.f32 %0, %1, %2;" : "=r"(r) : "f"(b), "f"(a));
    return r;
}
__device__ __forceinline__ void sts_v2(uint32_t addr, uint32_t r0, uint32_t r1) {
    asm volatile("st.shared.v2.b32 [%0], {%1, %2};" :: "r"(addr), "r"(r0), "r"(r1) : "memory");
}
__device__ __forceinline__ void ldsm_x4(uint32_t addr, uint32_t& r0, uint32_t& r1,
                                        uint32_t& r2, uint32_t& r3) {
    asm volatile("ldmatrix.sync.aligned.m8n8.x4.shared.b16 {%0,%1,%2,%3}, [%4];"
                 : "=r"(r0), "=r"(r1), "=r"(r2), "=r"(r3) : "r"(addr));
}
__device__ __forceinline__ void ldsm_x4_t(uint32_t addr, uint32_t& r0, uint32_t& r1,
                                          uint32_t& r2, uint32_t& r3) {
    asm volatile("ldmatrix.sync.aligned.m8n8.x4.trans.shared.b16 {%0,%1,%2,%3}, [%4];"
                 : "=r"(r0), "=r"(r1), "=r"(r2), "=r"(r3) : "r"(addr));
}
__device__ __forceinline__ void mma16816(float* d, uint32_t a0, uint32_t a1, uint32_t a2,
                                         uint32_t a3, uint32_t b0, uint32_t b1) {
    asm volatile(
        "mma.sync.aligned.m16n8k16.row.col.f32.bf16.bf16.f32 "
        "{%0,%1,%2,%3}, {%4,%5,%6,%7}, {%8,%9}, {%0,%1,%2,%3};"
        : "+f"(d[0]), "+f"(d[1]), "+f"(d[2]), "+f"(d[3])
        : "r"(a0), "r"(a1), "r"(a2), "r"(a3), "r"(b0), "r"(b1));
}

// ---------------- main kernel ----------------
__global__ __launch_bounds__(THREADS, 2)
void graph_loss_main(const float* __restrict__ A, const float* __restrict__ F,
                     float* __restrict__ out) {
    extern __shared__ __align__(1024) char smem[];
    const uint32_t sb = smem_u32(smem);

    const int b    = blockIdx.y;
    const int tile = blockIdx.x;
    const int tid  = threadIdx.x;
    const int wid  = tid >> 5;
    const int lane = tid & 31;

    // ---- stage F bf16 node-major [k][16 dims], 32-B rows, unit-swizzled ----
    {
        const float4* F4 = (const float4*)(F + (size_t)b * NN * ND);
        for (int i = tid; i < NN * ND / 4; i += THREADS) {
            const int k = i >> 2, q = i & 3;
            float4 v = F4[i];
            uint32_t lo = cvt2(v.x, v.y), hi = cvt2(v.z, v.w);
            uint32_t off = (uint32_t)(k * 32) +
                           ((uint32_t)(((q >> 1) ^ ((k >> 2) & 1)) << 4)) +
                           ((uint32_t)((q & 1) << 3));
            sts_v2(sb + SM_FT + off, lo, hi);
        }
    }
    __syncthreads();

    const int lrow = lane >> 4;
    const int lq   = lane & 15;
    const int lm   = lane >> 3;
    const int lr   = lane & 7;
    const int arow = ((lm & 1) << 3) + lr;        // A frag row 0..15
    const int ac   = lm >> 1;                     // A frag k-half
    const int bk   = ((lm & 1) << 3) + lr;        // B (trans) k-row
    const int bu   = lm >> 1;                     // B n-half unit
    const uint32_t bbase = sb + SM_FT +
        (uint32_t)(bk * 32 + ((bu ^ ((bk >> 2) & 1)) << 4));  // lane-constant

    const float C1 = 0.2f / (float)(NN * NN);
    const float C2 = 0.1f / (float)NN;
    const float C3 = 0.1f / (float)(NN * NN);

    float* deg_sh = (float*)(smem + SM_DEG);
    float* ws2    = (float*)(smem + SM_WS2);
    float* wc     = (float*)(smem + SM_WC);
    float* af     = (float*)(smem + SM_AF);
    int*   lastf  = (int*)(smem + SM_LAST);

    unsigned long long s22 = 0ULL;    // accumulates across both halves
    float tsum = 0.0f;                // thread 0 only: loss partial across halves

#pragma unroll 1
    for (int half = 0; half < 2; ++half) {
        const int row0 = tile * TILE_M + half * 128;
        const float* Arow = A + ((size_t)b * NN + row0 + wid * 16) * NN;
        const uint32_t ab0 = sb + SM_A + wid * 4096;       // chunk-parity buffers

        float D0[4] = {0.f, 0.f, 0.f, 0.f};   // dims 0-7
        float D1[4] = {0.f, 0.f, 0.f, 0.f};   // dims 8-15
        float D2[4] = {0.f, 0.f, 0.f, 0.f};   // deg (B = ones)

        auto load8 = [&](float4* v, int ch) {
            const int c0 = ch * CHUNK;
#pragma unroll
            for (int p = 0; p < 8; ++p)
                v[p] = __ldcs((const float4*)(Arow + (size_t)(2 * p + lrow) * NN + c0) + lq);
        };
        auto process = [&](const float4* v, int ch) {
            const uint32_t a_base = ab0 + (uint32_t)((ch & 1) * 2048);
#pragma unroll
            for (int p = 0; p < 8; ++p) {
                unsigned long long p0 = pack2(v[p].x, v[p].y);
                unsigned long long p1 = pack2(v[p].z, v[p].w);
                s22 = fma2(p0, p0, s22);
                s22 = fma2(p1, p1, s22);
                const int row = 2 * p + lrow;
                uint32_t byte = (uint32_t)(lq * 8) ^ ((uint32_t)(row & 7) << 4);
                sts_v2(a_base + row * 128 + byte, cvt2(v[p].x, v[p].y), cvt2(v[p].z, v[p].w));
            }
            __syncwarp();     // STS visible before ldsm; also orders prev-chunk ldsm vs buffer reuse
#pragma unroll
            for (int kk = 0; kk < 4; ++kk) {
                uint32_t abyte = (uint32_t)(kk * 32 + ac * 16) ^ ((uint32_t)(arow & 7) << 4);
                uint32_t a0, a1, a2, a3;
                ldsm_x4(a_base + arow * 128 + abyte, a0, a1, a2, a3);

                uint32_t b0, b1, b2, b3;
                ldsm_x4_t(bbase + (uint32_t)(ch * 2048 + kk * 512), b0, b1, b2, b3);

                mma16816(D0, a0, a1, a2, a3, b0, b1);
                mma16816(D1, a0, a1, a2, a3, b2, b3);
                mma16816(D2, a0, a1, a2, a3, BONES, BONES);   // row degrees
            }
        };

        // ---- software-pipelined main loop: double-buffered register loads ----
        float4 va[8], vb[8];
        load8(va, 0);
#pragma unroll 1
        for (int ch = 0; ch < NCHUNK; ch += 2) {
            load8(vb, ch + 1);
            process(va, ch);
            if (ch + 2 < NCHUNK) load8(va, ch + 2);
            process(vb, ch + 1);
        }

        // ---- deg from MMA fragments (all columns equal; quad-leader writes) ----
        if ((lane & 3) == 0) {
            const int g = lane >> 2;
            deg_sh[wid * 16 + g]     = D2[0];
            deg_sh[wid * 16 + g + 8] = D2[2];
        }
        // ---- spill af fragments to SMEM ----
        {
            const int g  = lane >> 2;
            const int cc = (lane & 3) * 2;
            float2* afr;
            afr = (float2*)&af[(wid * 16 + g) * 16 + cc];         *afr = make_float2(D0[0], D0[1]);
            afr = (float2*)&af[(wid * 16 + g + 8) * 16 + cc];     *afr = make_float2(D0[2], D0[3]);
            afr = (float2*)&af[(wid * 16 + g) * 16 + cc + 8];     *afr = make_float2(D1[0], D1[1]);
            afr = (float2*)&af[(wid * 16 + g + 8) * 16 + cc + 8]; *afr = make_float2(D1[2], D1[3]);
        }
        __syncthreads();

        // ---- per-row loss (threads 0..127), warp reduce ----
        if (tid < 128) {
            const int n = tid;
            const float4* fp = (const float4*)(F + ((size_t)b * NN + row0 + n) * ND);
            float4 f0 = fp[0], f1 = fp[1], f2 = fp[2], f3 = fp[3];
            const float* afn = &af[n * 16];

            float ff = f0.x * f0.x + f0.y * f0.y + f0.z * f0.z + f0.w * f0.w +
                       f1.x * f1.x + f1.y * f1.y + f1.z * f1.z + f1.w * f1.w +
                       f2.x * f2.x + f2.y * f2.y + f2.z * f2.z + f2.w * f2.w +
                       f3.x * f3.x + f3.y * f3.y + f3.z * f3.z + f3.w * f3.w;
            float dt = f0.x * afn[0]  + f0.y * afn[1]  + f0.z * afn[2]  + f0.w * afn[3] +
                       f1.x * afn[4]  + f1.y * afn[5]  + f1.z * afn[6]  + f1.w * afn[7] +
                       f2.x * afn[8]  + f2.y * afn[9]  + f2.z * afn[10] + f2.w * afn[11] +
                       f3.x * afn[12] + f3.y * afn[13] + f3.z * afn[14] + f3.w * afn[15];
            const float dn = deg_sh[n];
            float c = C1 * (dn * ff - dt) - C2 * logf(dn + 1e-12f);
#pragma unroll
            for (int off = 16; off; off >>= 1) c += __shfl_xor_sync(0xffffffffu, c, off);
            if (lane == 0) wc[tid >> 5] = c;
        }
        __syncthreads();
        if (tid == 0) tsum += wc[0] + wc[1] + wc[2] + wc[3];
    }

    // ---- s2 reduction (accumulated over both halves) ----
    {
        float lo, hi;
        unpack2(s22, lo, hi);
        float s2t = lo + hi;
#pragma unroll
        for (int off = 16; off; off >>= 1) s2t += __shfl_xor_sync(0xffffffffu, s2t, off);
        if (lane == 0) ws2[wid] = s2t;
    }
    __syncthreads();

    // ---- write partial; last CTA reduces ----
    if (tid == 0) {
        float s2sum = 0.f;
#pragma unroll
        for (int w = 0; w < WARPS; w++) s2sum += ws2[w];
        g_scratch[b * TILES + tile] = tsum + C3 * s2sum;
        __threadfence();
        unsigned int prev = atomicAdd(&g_count, 1u);
        *lastf = (prev == NCTAS - 1) ? 1 : 0;
    }
    __syncthreads();
    if (*lastf) {
        __threadfence();
        if (tid < NB) {
            float s = 0.f;
#pragma unroll
            for (int k = 0; k < TILES; k++) s += __ldcg(&g_scratch[tid * TILES + k]);
            out[tid] = s;
        }
        if (tid == 0) g_count = 0;
    }
}

extern "C" void kernel_launch(void* const* d_in, const int* in_sizes, int n_in,
                              void* d_out, int out_size) {
    const float* A = (const float*)d_in[0];   // out_adj  [64,1024,1024]
    const float* F = (const float*)d_in[1];   // features [64,1024,16]
    float* out = (float*)d_out;               // [64] fp32

    cudaFuncSetAttribute(graph_loss_main,
                         cudaFuncAttributeMaxDynamicSharedMemorySize, SMEM_TOTAL);
    dim3 grid(TILES, NB);
    graph_loss_main<<<grid, THREADS, SMEM_TOTAL>>>(A, F, out);
}

// round 16
// speedup vs baseline: 1.2880x; 1.0329x over previous
#include <cuda_runtime.h>
#include <cuda_bf16.h>
#include <cstdint>

#define NB 64
#define NN 1024
#define ND 16
#define TILE_M 256              // rows per CTA (two 128-row halves)
#define TILES (NN / TILE_M)     // 4
#define NCTAS (NB * TILES)      // 256  -> single wave at 2 CTAs/SM
#define THREADS 256
#define WARPS 8
#define CHUNK 64
#define NCHUNK (NN / CHUNK)     // 16

// ---- shared memory layout (byte offsets) ----
#define SM_FT   0               // F bf16 [1024 nodes][16 dims], swizzled 32-B rows: 32768 B
#define SM_A    32768           // A-tiles bf16: 8 warps x 2 bufs x 2048 B = 32768 B
#define SM_AF   65536           // af fp32 [128][16]: 8192 B
#define SM_DEG  73728           // 128 f32
#define SM_WS2  74240           // 8 f32
#define SM_WC   74272           // 4 f32
#define SM_LAST 74288           // 1 int
#define SMEM_TOTAL 74368

#define BONES 0x3F803F80u       // bf16x2 (1.0, 1.0)

__device__ float g_scratch[NCTAS];
__device__ unsigned int g_count;   // zero-init; reset by last CTA each launch

// ---------------- helpers ----------------
__device__ __forceinline__ uint32_t smem_u32(const void* p) {
    uint32_t a;
    asm("{ .reg .u64 t; cvta.to.shared.u64 t, %1; cvt.u32.u64 %0, t; }" : "=r"(a) : "l"(p));
    return a;
}
__device__ __forceinline__ unsigned long long fma2(unsigned long long a, unsigned long long b,
                                                   unsigned long long c) {
    unsigned long long d;
    asm("fma.rn.f32x2 %0, %1, %2, %3;" : "=l"(d) : "l"(a), "l"(b), "l"(c));
    return d;
}
__device__ __forceinline__ unsigned long long pack2(float x, float y) {
    unsigned long long d;
    asm("mov.b64 %0, {%1, %2};" : "=l"(d) : "f"(x), "f"(y));
    return d;
}
__device__ __forceinline__ void unpack2(unsigned long long v, float& x, float& y) {
    asm("mov.b64 {%0, %1}, %2;" : "=f"(x), "=f"(y) : "l"(v));
}
__device__ __forceinline__ uint32_t cvt2(float a, float b) {
    uint32_t r;
    asm("cvt.rn.bf16x2.f32 %0, %1, %2;" : "=r"(r) : "f"(b), "f"(a));
    return r;
}
__device__ __forceinline__ void sts_v2(uint32_t addr, uint32_t r0, uint32_t r1) {
    asm volatile("st.shared.v2.b32 [%0], {%1, %2};" :: "r"(addr), "r"(r0), "r"(r1) : "memory");
}
__device__ __forceinline__ void ldsm_x4(uint32_t addr, uint32_t& r0, uint32_t& r1,
                                        uint32_t& r2, uint32_t& r3) {
    asm volatile("ldmatrix.sync.aligned.m8n8.x4.shared.b16 {%0,%1,%2,%3}, [%4];"
                 : "=r"(r0), "=r"(r1), "=r"(r2), "=r"(r3) : "r"(addr));
}
__device__ __forceinline__ void ldsm_x4_t(uint32_t addr, uint32_t& r0, uint32_t& r1,
                                          uint32_t& r2, uint32_t& r3) {
    asm volatile("ldmatrix.sync.aligned.m8n8.x4.trans.shared.b16 {%0,%1,%2,%3}, [%4];"
                 : "=r"(r0), "=r"(r1), "=r"(r2), "=r"(r3) : "r"(addr));
}
__device__ __forceinline__ void mma16816(float* d, uint32_t a0, uint32_t a1, uint32_t a2,
                                         uint32_t a3, uint32_t b0, uint32_t b1) {
    asm volatile(
        "mma.sync.aligned.m16n8k16.row.col.f32.bf16.bf16.f32 "
        "{%0,%1,%2,%3}, {%4,%5,%6,%7}, {%8,%9}, {%0,%1,%2,%3};"
        : "+f"(d[0]), "+f"(d[1]), "+f"(d[2]), "+f"(d[3])
        : "r"(a0), "r"(a1), "r"(a2), "r"(a3), "r"(b0), "r"(b1));
}

// ---------------- main kernel ----------------
__global__ __launch_bounds__(THREADS, 2)
void graph_loss_main(const float* __restrict__ A, const float* __restrict__ F,
                     float* __restrict__ out) {
    extern __shared__ __align__(1024) char smem[];
    const uint32_t sb = smem_u32(smem);

    const int b    = blockIdx.y;
    const int tile = blockIdx.x;
    const int tid  = threadIdx.x;
    const int wid  = tid >> 5;
    const int lane = tid & 31;

    // ---- stage F bf16 node-major [k][16 dims], 32-B rows, unit-swizzled ----
    {
        const float4* F4 = (const float4*)(F + (size_t)b * NN * ND);
        for (int i = tid; i < NN * ND / 4; i += THREADS) {
            const int k = i >> 2, q = i & 3;
            float4 v = F4[i];
            uint32_t lo = cvt2(v.x, v.y), hi = cvt2(v.z, v.w);
            uint32_t off = (uint32_t)(k * 32) +
                           ((uint32_t)(((q >> 1) ^ ((k >> 2) & 1)) << 4)) +
                           ((uint32_t)((q & 1) << 3));
            sts_v2(sb + SM_FT + off, lo, hi);
        }
    }
    __syncthreads();

    const int lrow = lane >> 4;
    const int lq   = lane & 15;
    const int lm   = lane >> 3;
    const int lr   = lane & 7;
    const int arow = ((lm & 1) << 3) + lr;        // A frag row 0..15
    const int ac   = lm >> 1;                     // A frag k-half
    const int bk   = ((lm & 1) << 3) + lr;        // B (trans) k-row
    const int bu   = lm >> 1;                     // B n-half unit
    const uint32_t bbase = sb + SM_FT +
        (uint32_t)(bk * 32 + ((bu ^ ((bk >> 2) & 1)) << 4));  // lane-constant

    const float C1 = 0.2f / (float)(NN * NN);
    const float C2 = 0.1f / (float)NN;
    const float C3 = 0.1f / (float)(NN * NN);

    float* deg_sh = (float*)(smem + SM_DEG);
    float* ws2    = (float*)(smem + SM_WS2);
    float* wc     = (float*)(smem + SM_WC);
    float* af     = (float*)(smem + SM_AF);
    int*   lastf  = (int*)(smem + SM_LAST);

    unsigned long long s22 = 0ULL;    // accumulates across both halves
    float tsum = 0.0f;                // thread 0 only: loss partial across halves

#pragma unroll 1
    for (int half = 0; half < 2; ++half) {
        const int row0 = tile * TILE_M + half * 128;
        const float* Arow = A + ((size_t)b * NN + row0 + wid * 16) * NN;
        const uint32_t abT0 = sb + SM_A + wid * 4096;
        const uint32_t abT1 = abT0 + 2048;

        float D0[4] = {0.f, 0.f, 0.f, 0.f};   // dims 0-7
        float D1[4] = {0.f, 0.f, 0.f, 0.f};   // dims 8-15
        float D2[4] = {0.f, 0.f, 0.f, 0.f};   // deg (B = ones)

        auto load8 = [&](float4* v, int ch) {
            const int c0 = ch * CHUNK;
#pragma unroll
            for (int p = 0; p < 8; ++p)
                v[p] = __ldcs((const float4*)(Arow + (size_t)(2 * p + lrow) * NN + c0) + lq);
        };
        // s2 accumulate + bf16 convert + STS into tile (no ldsm/MMA)
        auto ingest = [&](const float4* v, uint32_t a_base) {
#pragma unroll
            for (int p = 0; p < 8; ++p) {
                unsigned long long p0 = pack2(v[p].x, v[p].y);
                unsigned long long p1 = pack2(v[p].z, v[p].w);
                s22 = fma2(p0, p0, s22);
                s22 = fma2(p1, p1, s22);
                const int row = 2 * p + lrow;
                uint32_t byte = (uint32_t)(lq * 8) ^ ((uint32_t)(row & 7) << 4);
                sts_v2(a_base + row * 128 + byte, cvt2(v[p].x, v[p].y), cvt2(v[p].z, v[p].w));
            }
        };
        // ldsm + MMA only
        auto consume = [&](int ch, uint32_t a_base) {
#pragma unroll
            for (int kk = 0; kk < 4; ++kk) {
                uint32_t abyte = (uint32_t)(kk * 32 + ac * 16) ^ ((uint32_t)(arow & 7) << 4);
                uint32_t a0, a1, a2, a3;
                ldsm_x4(a_base + arow * 128 + abyte, a0, a1, a2, a3);

                uint32_t b0, b1, b2, b3;
                ldsm_x4_t(bbase + (uint32_t)(ch * 2048 + kk * 512), b0, b1, b2, b3);

                mma16816(D0, a0, a1, a2, a3, b0, b1);
                mma16816(D1, a0, a1, a2, a3, b2, b3);
                mma16816(D2, a0, a1, a2, a3, BONES, BONES);   // row degrees
            }
        };

        // ---- pipelined loop: all LDGs issued before the MMA-heavy consumes ----
        float4 va[8], vb[8];
        load8(va, 0);
        load8(vb, 1);
#pragma unroll 1
        for (int ch = 0; ch < NCHUNK; ch += 2) {
            ingest(va, abT0);
            if (ch + 2 < NCHUNK) load8(va, ch + 2);
            ingest(vb, abT1);
            if (ch + 3 < NCHUNK) load8(vb, ch + 3);
            __syncwarp();               // STS of both tiles visible before ldsm
            consume(ch,     abT0);
            consume(ch + 1, abT1);
            __syncwarp();               // ldsm done before next iteration's STS reuse
        }

        // ---- deg from MMA fragments (all columns equal; quad-leader writes) ----
        if ((lane & 3) == 0) {
            const int g = lane >> 2;
            deg_sh[wid * 16 + g]     = D2[0];
            deg_sh[wid * 16 + g + 8] = D2[2];
        }
        // ---- spill af fragments to SMEM ----
        {
            const int g  = lane >> 2;
            const int cc = (lane & 3) * 2;
            float2* afr;
            afr = (float2*)&af[(wid * 16 + g) * 16 + cc];         *afr = make_float2(D0[0], D0[1]);
            afr = (float2*)&af[(wid * 16 + g + 8) * 16 + cc];     *afr = make_float2(D0[2], D0[3]);
            afr = (float2*)&af[(wid * 16 + g) * 16 + cc + 8];     *afr = make_float2(D1[0], D1[1]);
            afr = (float2*)&af[(wid * 16 + g + 8) * 16 + cc + 8]; *afr = make_float2(D1[2], D1[3]);
        }
        __syncthreads();

        // ---- per-row loss (threads 0..127), warp reduce ----
        if (tid < 128) {
            const int n = tid;
            const float4* fp = (const float4*)(F + ((size_t)b * NN + row0 + n) * ND);
            float4 f0 = fp[0], f1 = fp[1], f2 = fp[2], f3 = fp[3];
            const float* afn = &af[n * 16];

            float ff = f0.x * f0.x + f0.y * f0.y + f0.z * f0.z + f0.w * f0.w +
                       f1.x * f1.x + f1.y * f1.y + f1.z * f1.z + f1.w * f1.w +
                       f2.x * f2.x + f2.y * f2.y + f2.z * f2.z + f2.w * f2.w +
                       f3.x * f3.x + f3.y * f3.y + f3.z * f3.z + f3.w * f3.w;
            float dt = f0.x * afn[0]  + f0.y * afn[1]  + f0.z * afn[2]  + f0.w * afn[3] +
                       f1.x * afn[4]  + f1.y * afn[5]  + f1.z * afn[6]  + f1.w * afn[7] +
                       f2.x * afn[8]  + f2.y * afn[9]  + f2.z * afn[10] + f2.w * afn[11] +
                       f3.x * afn[12] + f3.y * afn[13] + f3.z * afn[14] + f3.w * afn[15];
            const float dn = deg_sh[n];
            float c = C1 * (dn * ff - dt) - C2 * logf(dn + 1e-12f);
#pragma unroll
            for (int off = 16; off; off >>= 1) c += __shfl_xor_sync(0xffffffffu, c, off);
            if (lane == 0) wc[tid >> 5] = c;
        }
        __syncthreads();
        if (tid == 0) tsum += wc[0] + wc[1] + wc[2] + wc[3];
    }

    // ---- s2 reduction (accumulated over both halves) ----
    {
        float lo, hi;
        unpack2(s22, lo, hi);
        float s2t = lo + hi;
#pragma unroll
        for (int off = 16; off; off >>= 1) s2t += __shfl_xor_sync(0xffffffffu, s2t, off);
        if (lane == 0) ws2[wid] = s2t;
    }
    __syncthreads();

    // ---- write partial; last CTA reduces ----
    if (tid == 0) {
        float s2sum = 0.f;
#pragma unroll
        for (int w = 0; w < WARPS; w++) s2sum += ws2[w];
        g_scratch[b * TILES + tile] = tsum + C3 * s2sum;
        __threadfence();
        unsigned int prev = atomicAdd(&g_count, 1u);
        *lastf = (prev == NCTAS - 1) ? 1 : 0;
    }
    __syncthreads();
    if (*lastf) {
        __threadfence();
        if (tid < NB) {
            float s = 0.f;
#pragma unroll
            for (int k = 0; k < TILES; k++) s += __ldcg(&g_scratch[tid * TILES + k]);
            out[tid] = s;
        }
        if (tid == 0) g_count = 0;
    }
}

extern "C" void kernel_launch(void* const* d_in, const int* in_sizes, int n_in,
                              void* d_out, int out_size) {
    const float* A = (const float*)d_in[0];   // out_adj  [64,1024,1024]
    const float* F = (const float*)d_in[1];   // features [64,1024,16]
    float* out = (float*)d_out;               // [64] fp32

    cudaFuncSetAttribute(graph_loss_main,
                         cudaFuncAttributeMaxDynamicSharedMemorySize, SMEM_TOTAL);
    dim3 grid(TILES, NB);
    graph_loss_main<<<grid, THREADS, SMEM_TOTAL>>>(A, F, out);
}